// round 4
// baseline (speedup 1.0000x reference)
#include <cuda_runtime.h>

typedef unsigned long long u64;

#define Bn 256
#define Tn 256
#define Sn 20
#define NROWS (Bn*Tn)   // 65536

__device__ float g_zx[NROWS * 96];   // zx[row][96] = h_inner[row] @ Wo + bo

// ---------- packed f32x2 helpers ----------
__device__ __forceinline__ u64 ffma2(u64 a, u64 b, u64 c){
    u64 d;
    asm("fma.rn.f32x2 %0, %1, %2, %3;" : "=l"(d) : "l"(a), "l"(b), "l"(c));
    return d;
}
__device__ __forceinline__ u64 add2(u64 a, u64 b){
    u64 d;
    asm("add.rn.f32x2 %0, %1, %2;" : "=l"(d) : "l"(a), "l"(b));
    return d;
}
__device__ __forceinline__ u64 pk2(float lo, float hi){
    u64 r; asm("mov.b64 %0, {%1, %2};" : "=l"(r) : "f"(lo), "f"(hi)); return r;
}
__device__ __forceinline__ void up2(u64 v, float& lo, float& hi){
    asm("mov.b64 {%0, %1}, %2;" : "=f"(lo), "=f"(hi) : "l"(v));
}

// ---------- slim activations (exact limits, no clamps, no NaN) ----------
__device__ __forceinline__ float ex2f(float x){
    float r; asm("ex2.approx.ftz.f32 %0, %1;" : "=f"(r) : "f"(x)); return r;
}
__device__ __forceinline__ float rcpf(float x){
    float r; asm("rcp.approx.ftz.f32 %0, %1;" : "=f"(r) : "f"(x)); return r;
}
__device__ __forceinline__ float sigf(float x){
    return rcpf(1.0f + ex2f(-1.4426950408889634f * x));
}
__device__ __forceinline__ float tanh_f(float x){
    return fmaf(-2.0f, rcpf(1.0f + ex2f(2.8853900817779268f * x)), 1.0f);
}

// =====================================================================
// Inner LSTM: 65536 rows, S=20, U1=32, D=1.
// Block = 256 threads = 32 row-pair columns x 8 unit-groups (4 units each).
// smem trimmed to 50KB (x read directly from gmem, prefetched) so 4 blocks/SM
// = 8 warps/SMSP. __launch_bounds__(256,4) caps regs at 64 (live ~60).
// =====================================================================
__global__ void __launch_bounds__(256, 4) inner_kernel(
    const float* __restrict__ x,  const float* __restrict__ Wi,
    const float* __restrict__ Ui, const float* __restrict__ bi,
    const float* __restrict__ Wo, const float* __restrict__ bo)
{
    extern __shared__ char smem[];
    float* wuf = (float*)smem;            // dup Ui [k][u][g][2]: 8192 f (32KB)
    float* wif = wuf + 8192;              // dup Wi [u][g][2]: 256 f
    float* bif = wif + 256;               // dup bi [u][g][2]: 256 f
    u64*  hsm  = (u64*)(bif + 256);       // h [2][32 u][32 col]: 2048 u64 (16KB)

    const int tid = threadIdx.x;
    const int col = tid & 31;             // row-pair column (warp-lane)
    const int ug  = tid >> 5;             // unit group 0..7 (= warp id)
    const int ubase = ug * 4;

    // cooperative load + duplicate weights (gate order i,f,g,o: Ui col = g*32+u)
    for (int idx = tid; idx < 4096; idx += 256){
        int k = idx >> 7, cw = idx & 127;
        int g = cw >> 5,  u  = cw & 31;
        float w = Ui[idx];
        int o = (((k << 5) + u) * 4 + g) * 2;
        wuf[o] = w; wuf[o + 1] = w;
    }
    if (tid < 128){
        int g = tid >> 5, u = tid & 31;
        int o = (u * 4 + g) * 2;
        float w = Wi[tid]; wif[o] = w; wif[o + 1] = w;
        float b = bi[tid]; bif[o] = b; bif[o + 1] = b;
    }
    for (int i = tid; i < 1024; i += 256) hsm[i] = 0ULL;  // h0 = 0 (buf 0)
    __syncthreads();

    const ulonglong2* wu2 = (const ulonglong2*)wuf;
    const ulonglong2* wi2 = (const ulonglong2*)wif;
    const ulonglong2* bi2 = (const ulonglong2*)bif;

    float cA[4], cB[4];
    #pragma unroll
    for (int u8 = 0; u8 < 4; u8++){ cA[u8] = 0.f; cB[u8] = 0.f; }

    const long pair = (long)blockIdx.x * 32 + col;
    const float* x0p = x + (2 * pair) * Sn;
    const float* x1p = x + (2 * pair + 1) * Sn;
    float xn0 = __ldg(x0p), xn1 = __ldg(x1p);

    #pragma unroll 1
    for (int s = 0; s < Sn; s++){
        u64 xv = pk2(xn0, xn1);
        int sp = (s + 1 < Sn) ? s + 1 : s;
        xn0 = __ldg(x0p + sp); xn1 = __ldg(x1p + sp);   // branch-free prefetch
        const u64* hb = hsm + ((s & 1) << 10);
        u64*       hw = hsm + (((s + 1) & 1) << 10);

        u64 a[4][4];
        #pragma unroll
        for (int u8 = 0; u8 < 4; u8++){
            int u = ubase + u8;
            ulonglong2 wA = wi2[u * 2], wB = wi2[u * 2 + 1];
            ulonglong2 bA = bi2[u * 2], bB = bi2[u * 2 + 1];
            a[u8][0] = ffma2(xv, wA.x, bA.x);
            a[u8][1] = ffma2(xv, wA.y, bA.y);
            a[u8][2] = ffma2(xv, wB.x, bB.x);
            a[u8][3] = ffma2(xv, wB.y, bB.y);
        }
        #pragma unroll 8
        for (int k = 0; k < 32; k++){
            u64 hk = hb[(k << 5) + col];
            #pragma unroll
            for (int u8 = 0; u8 < 4; u8++){
                int wo_ = ((k << 5) + ubase + u8) << 1;
                ulonglong2 w01 = wu2[wo_], w23 = wu2[wo_ + 1];
                a[u8][0] = ffma2(hk, w01.x, a[u8][0]);
                a[u8][1] = ffma2(hk, w01.y, a[u8][1]);
                a[u8][2] = ffma2(hk, w23.x, a[u8][2]);
                a[u8][3] = ffma2(hk, w23.y, a[u8][3]);
            }
        }
        #pragma unroll
        for (int u8 = 0; u8 < 4; u8++){
            float zi0, zi1, zf0, zf1, zg0, zg1, zo0, zo1;
            up2(a[u8][0], zi0, zi1);
            up2(a[u8][1], zf0, zf1);
            up2(a[u8][2], zg0, zg1);
            up2(a[u8][3], zo0, zo1);
            float i0 = sigf(zi0),   i1 = sigf(zi1);
            float f0 = sigf(zf0),   f1 = sigf(zf1);
            float g0 = tanh_f(zg0), g1 = tanh_f(zg1);
            float o0 = sigf(zo0),   o1 = sigf(zo1);
            float c0 = f0 * cA[u8] + i0 * g0;
            float c1 = f1 * cB[u8] + i1 * g1;
            cA[u8] = c0; cB[u8] = c1;
            hw[((ubase + u8) << 5) + col] = pk2(o0 * tanh_f(c0), o1 * tanh_f(c1));
        }
        __syncthreads();
    }

    // epilogue: zx = h_final @ Wo + bo (final h in buffer 0, Sn even).
    // unit-group ug computes 12 of the 96 output columns.
    const u64* hf = hsm;
    const long r0 = 2 * pair, r1 = r0 + 1;
    float* z0p = g_zx + r0 * 96 + ug * 12;
    float* z1p = g_zx + r1 * 96 + ug * 12;
    #pragma unroll 1
    for (int c4 = 0; c4 < 3; c4++){
        float4 b4 = __ldg((const float4*)(bo + ug * 12 + c4 * 4));
        u64 ac0 = pk2(b4.x, b4.x), ac1 = pk2(b4.y, b4.y);
        u64 ac2 = pk2(b4.z, b4.z), ac3 = pk2(b4.w, b4.w);
        #pragma unroll 4
        for (int k = 0; k < 32; k++){
            u64 hk = hf[(k << 5) + col];
            float4 w4 = __ldg((const float4*)(Wo + k * 96 + ug * 12 + c4 * 4));
            ac0 = ffma2(hk, pk2(w4.x, w4.x), ac0);
            ac1 = ffma2(hk, pk2(w4.y, w4.y), ac1);
            ac2 = ffma2(hk, pk2(w4.z, w4.z), ac2);
            ac3 = ffma2(hk, pk2(w4.w, w4.w), ac3);
        }
        float a0l,a0h,a1l,a1h,a2l,a2h,a3l,a3h;
        up2(ac0,a0l,a0h); up2(ac1,a1l,a1h); up2(ac2,a2l,a2h); up2(ac3,a3l,a3h);
        *(float4*)(z0p + c4 * 4) = make_float4(a0l, a1l, a2l, a3l);
        *(float4*)(z1p + c4 * 4) = make_float4(a0h, a1h, a2h, a3h);
    }
}

// =====================================================================
// Outer LSTM + dense head: one warp per batch row. Register weights.
// 4 independent accumulator chains (depth 6+2 vs 24), branch-free
// distance-2 prefetch (clamped index). Zero LDS, zero branches in loop.
// =====================================================================
__global__ void __launch_bounds__(32) outer_kernel(
    const int*   __restrict__ lengths,
    const float* __restrict__ Uo,
    const float* __restrict__ Wd,
    const float* __restrict__ bd,
    float*       __restrict__ out)
{
    const int l  = threadIdx.x;
    const int la = (l < 24) ? l : 0;       // clamped lane
    const int b  = blockIdx.x;

    u64 w_if[24], w_go[24];
    #pragma unroll
    for (int k = 0; k < 24; k++){
        const float* row = Uo + k * 96;
        w_if[k] = pk2(__ldg(row + la),      __ldg(row + 24 + la));
        w_go[k] = pk2(__ldg(row + 48 + la), __ldg(row + 72 + la));
    }

    const int len = lengths[b];            // in [1, T]
    const float* zr = g_zx + (size_t)b * Tn * 96;

    // prefetch ring, depth 2
    u64 pA[2], pB[2];
    {
        pA[0] = pk2(zr[la], zr[24 + la]);
        pB[0] = pk2(zr[48 + la], zr[72 + la]);
        const float* z1 = zr + ((len > 1) ? 96 : 0);
        pA[1] = pk2(z1[la], z1[24 + la]);
        pB[1] = pk2(z1[48 + la], z1[72 + la]);
    }

    const u64 Z2 = 0ULL;  // packed (0,0)
    float h = 0.f, c = 0.f;

    for (int t = 0; t < len; t++){
        u64 zA = pA[t & 1], zB = pB[t & 1];
        // branch-free prefetch of step t+2 (clamped)
        {
            int tp = (t + 2 < len) ? t + 2 : len - 1;
            const float* zq = zr + (size_t)tp * 96;
            pA[t & 1] = pk2(zq[la], zq[24 + la]);
            pB[t & 1] = pk2(zq[48 + la], zq[72 + la]);
        }
        // 4 independent chains of depth 6
        u64 a0 = zA, a1 = Z2, a2 = Z2, a3 = Z2;
        u64 b0 = zB, b1 = Z2, b2 = Z2, b3 = Z2;
        #pragma unroll
        for (int j = 0; j < 6; j++){
            float h0 = __shfl_sync(0xffffffffu, h, j);
            float h1 = __shfl_sync(0xffffffffu, h, j + 6);
            float h2 = __shfl_sync(0xffffffffu, h, j + 12);
            float h3 = __shfl_sync(0xffffffffu, h, j + 18);
            u64 H0 = pk2(h0, h0), H1 = pk2(h1, h1);
            u64 H2 = pk2(h2, h2), H3 = pk2(h3, h3);
            a0 = ffma2(H0, w_if[j],      a0);  b0 = ffma2(H0, w_go[j],      b0);
            a1 = ffma2(H1, w_if[j + 6],  a1);  b1 = ffma2(H1, w_go[j + 6],  b1);
            a2 = ffma2(H2, w_if[j + 12], a2);  b2 = ffma2(H2, w_go[j + 12], b2);
            a3 = ffma2(H3, w_if[j + 18], a3);  b3 = ffma2(H3, w_go[j + 18], b3);
        }
        u64 zAf = add2(add2(a0, a1), add2(a2, a3));
        u64 zBf = add2(add2(b0, b1), add2(b2, b3));

        float zi, zf, zg, zo;
        up2(zAf, zi, zf);
        up2(zBf, zg, zo);
        float fi = sigf(zi), ff = sigf(zf), gg = tanh_f(zg), oo = sigf(zo);
        c = ff * c + fi * gg;
        h = oo * tanh_f(c);
    }

    // dense sigmoid head
    float p = (l < 24) ? h * __ldg(Wd + la) : 0.f;
    #pragma unroll
    for (int off = 16; off; off >>= 1) p += __shfl_xor_sync(0xffffffffu, p, off);
    if (l == 0) out[b] = sigf(p + bd[0]);
}

extern "C" void kernel_launch(void* const* d_in, const int* in_sizes, int n_in,
                              void* d_out, int out_size)
{
    const float* x       = (const float*)d_in[0];
    const int*   lengths = (const int*)  d_in[1];
    const float* Wi      = (const float*)d_in[2];
    const float* Ui      = (const float*)d_in[3];
    const float* bi      = (const float*)d_in[4];
    const float* Wo      = (const float*)d_in[5];
    const float* Uo      = (const float*)d_in[6];
    const float* bo      = (const float*)d_in[7];
    const float* Wd      = (const float*)d_in[8];
    const float* bd      = (const float*)d_in[9];
    float* out = (float*)d_out;

    // smem: wuf 32768 + wif 1024 + bif 1024 + hsm 16384 = 51200 (4 blocks/SM)
    const int smem_bytes = 51200;
    cudaFuncSetAttribute(inner_kernel,
                         cudaFuncAttributeMaxDynamicSharedMemorySize, smem_bytes);

    inner_kernel<<<1024, 256, smem_bytes>>>(x, Wi, Ui, bi, Wo, bo);
    outer_kernel<<<256, 32>>>(lengths, Uo, Wd, bd, out);
}